// round 6
// baseline (speedup 1.0000x reference)
#include <cuda_runtime.h>
#include <cstdint>
#include <cstddef>

// Problem constants (fixed by setup_inputs)
constexpr int B_  = 4;
constexpr int N_  = 2048;
constexpr int E_  = 1600;
constexpr int R_  = 448;
constexpr int H_  = 512;
constexpr int NH_ = 4;
constexpr int DH_ = 128;
constexpr int FF_ = 2048;   // 4*H
constexpr int P_  = 2;

typedef unsigned long long u64;

// packed f32x2 helpers (Blackwell sm_103a)
__device__ __forceinline__ void ffma2(u64& d, u64 a, u64 b) {
    asm("fma.rn.f32x2 %0, %1, %2, %0;" : "+l"(d) : "l"(a), "l"(b));
}
__device__ __forceinline__ u64 dup_f32(float x) {
    u64 r;
    asm("mov.b64 %0, {%1, %1};" : "=l"(r) : "f"(x));
    return r;
}
__device__ __forceinline__ void unpack_f32x2(float& lo, float& hi, u64 v) {
    asm("mov.b64 {%0, %1}, %2;" : "=f"(lo), "=f"(hi) : "l"(v));
}

// -------------------- scratch (__device__ globals; no allocs) ---------------
__device__ float g_x[(size_t)B_ * N_ * H_];
__device__ float g_q[(size_t)B_ * N_ * H_];
__device__ float g_k[(size_t)B_ * N_ * H_];
__device__ float g_v[(size_t)B_ * N_ * H_];
__device__ float g_o[(size_t)B_ * N_ * H_];
__device__ float g_t[(size_t)B_ * N_ * H_];
__device__ float g_y[(size_t)B_ * N_ * H_];
__device__ float g_h[(size_t)B_ * N_ * FF_];
__device__ float g_s[(size_t)B_ * NH_ * N_ * N_];   // 256 MB attention scores

// pointer bundle for fused-QKV launch (passed by value)
struct QKVArgs {
    const float* W[3];
    const float* bias[3];
    float* C[3];
};

// -------------------- build x = concat(vents, renc_w[rels]) ----------------
__global__ void build_x_kernel(const float* __restrict__ vents,
                               const int* __restrict__ rels,
                               const float* __restrict__ renc,
                               float* __restrict__ x) {
    size_t idx = (size_t)blockIdx.x * blockDim.x + threadIdx.x;
    if (idx >= (size_t)B_ * N_ * H_) return;
    int c = (int)(idx % H_);
    size_t t = idx / H_;
    int n = (int)(t % N_);
    int b = (int)(t / N_);
    float val;
    if (n < E_) {
        val = vents[((size_t)b * E_ + n) * H_ + c];
    } else {
        int rel = rels[b * R_ + (n - E_)];
        val = renc[(size_t)rel * H_ + c];
    }
    x[idx] = val;
}

// ------- 128x128x16 SGEMM (NN), double-buffered smem + FFMA2 mainloop -------
// EPI: 0 = +bias ; 1 = +bias then PReLU(alpha=extra[col]) ;
//      2 = +bias + extra[row*ldc+col] (residual) ; 3 = plain
// BMODE: 0 = none ; 1 = fused QKV (z selects W/bias/C from qkv args)
//        2 = AV batch: A += z*N*N, B/C += (z/NH)*N*H + (z%NH)*DH
constexpr int GBM = 128, GBN = 128, GBK = 16, GTM = 8, GTN = 8;

template <int EPI, int BMODE>
__global__ __launch_bounds__(256)
void sgemm_nn(const float* __restrict__ A, int lda,
              const float* __restrict__ Bm, int ldb,
              float* __restrict__ C, int ldc, int K,
              const float* __restrict__ bias,
              const float* __restrict__ extra,
              QKVArgs qkv = {}) {
    if (BMODE == 1) {
        int z = blockIdx.z;          // 0=Q, 1=K, 2=V
        Bm   = qkv.W[z];
        bias = qkv.bias[z];
        C    = qkv.C[z];
    } else if (BMODE == 2) {
        int z = blockIdx.z;
        A += (size_t)z * N_ * N_;
        size_t off = (size_t)(z / NH_) * N_ * H_ + (size_t)(z % NH_) * DH_;
        Bm += off;
        C  += off;
    }
    __shared__ alignas(16) float As[2][GBK][GBM];   // ping-pong; As[buf][k][m]
    __shared__ alignas(16) float Bs[2][GBK][GBN];   // Bs[buf][k][n]
    const int tid = threadIdx.x;
    const int tx = tid % 16, ty = tid / 16;
    const int rowBase = blockIdx.y * GBM;
    const int colBase = blockIdx.x * GBN;

    // A tile loaders: 128 rows x 16 cols = 512 float4, 2/thread
    const int aRow = tid >> 2;            // 0..63  (second pass +64)
    const int aCol = (tid & 3) * 4;       // 0,4,8,12
    // B tile loaders: 16 rows x 128 cols = 512 float4, 2/thread
    const int bRow = tid >> 5;            // 0..7   (second pass +8)
    const int bCol = (tid & 31) * 4;      // 0..124

    const float* Aptr0 = A + (size_t)(rowBase + aRow) * lda + aCol;
    const float* Aptr1 = Aptr0 + (size_t)64 * lda;
    const float* Bptr0 = Bm + (size_t)bRow * ldb + colBase + bCol;
    const float* Bptr1 = Bptr0 + (size_t)8 * ldb;

    // accumulators as packed f32x2 pairs: acc2[i][jj] = {acc[i][2jj], acc[i][2jj+1]}
    u64 acc2[GTM][GTN / 2];
#pragma unroll
    for (int i = 0; i < GTM; i++)
#pragma unroll
        for (int j = 0; j < GTN / 2; j++) acc2[i][j] = 0ull;

    // prologue: fetch tile 0 and stage into buffer 0
    {
        float4 a0 = *reinterpret_cast<const float4*>(Aptr0);
        float4 a1 = *reinterpret_cast<const float4*>(Aptr1);
        float4 b0 = *reinterpret_cast<const float4*>(Bptr0);
        float4 b1 = *reinterpret_cast<const float4*>(Bptr1);
        As[0][aCol + 0][aRow]      = a0.x;
        As[0][aCol + 1][aRow]      = a0.y;
        As[0][aCol + 2][aRow]      = a0.z;
        As[0][aCol + 3][aRow]      = a0.w;
        As[0][aCol + 0][aRow + 64] = a1.x;
        As[0][aCol + 1][aRow + 64] = a1.y;
        As[0][aCol + 2][aRow + 64] = a1.z;
        As[0][aCol + 3][aRow + 64] = a1.w;
        *reinterpret_cast<float4*>(&Bs[0][bRow][bCol])     = b0;
        *reinterpret_cast<float4*>(&Bs[0][bRow + 8][bCol]) = b1;
    }
    __syncthreads();

    int cur = 0;
    for (int k0 = 0; k0 < K; k0 += GBK) {
        const int nxt = cur ^ 1;
        const bool hasNext = (k0 + GBK) < K;

        // prefetch next tile (global -> regs), overlaps with compute below
        float4 a0, a1, b0, b1;
        if (hasNext) {
            a0 = *reinterpret_cast<const float4*>(Aptr0 + k0 + GBK);
            a1 = *reinterpret_cast<const float4*>(Aptr1 + k0 + GBK);
            b0 = *reinterpret_cast<const float4*>(Bptr0 + (size_t)(k0 + GBK) * ldb);
            b1 = *reinterpret_cast<const float4*>(Bptr1 + (size_t)(k0 + GBK) * ldb);
        }

        // compute on current buffer: 32 FFMA2 per k
#pragma unroll
        for (int k = 0; k < GBK; k++) {
            float4 ra0 = *reinterpret_cast<const float4*>(&As[cur][k][ty * GTM]);
            float4 ra1 = *reinterpret_cast<const float4*>(&As[cur][k][ty * GTM + 4]);
            const u64* rbp = reinterpret_cast<const u64*>(&Bs[cur][k][tx * GTN]);
            u64 rb2[4] = {rbp[0], rbp[1], rbp[2], rbp[3]};
            float ra[GTM] = {ra0.x, ra0.y, ra0.z, ra0.w, ra1.x, ra1.y, ra1.z, ra1.w};
#pragma unroll
            for (int i = 0; i < GTM; i++) {
                u64 a2 = dup_f32(ra[i]);
#pragma unroll
                for (int j = 0; j < GTN / 2; j++) ffma2(acc2[i][j], a2, rb2[j]);
            }
        }

        // stage next tile into the other buffer (no race: different buffer)
        if (hasNext) {
            As[nxt][aCol + 0][aRow]      = a0.x;
            As[nxt][aCol + 1][aRow]      = a0.y;
            As[nxt][aCol + 2][aRow]      = a0.z;
            As[nxt][aCol + 3][aRow]      = a0.w;
            As[nxt][aCol + 0][aRow + 64] = a1.x;
            As[nxt][aCol + 1][aRow + 64] = a1.y;
            As[nxt][aCol + 2][aRow + 64] = a1.z;
            As[nxt][aCol + 3][aRow + 64] = a1.w;
            *reinterpret_cast<float4*>(&Bs[nxt][bRow][bCol])     = b0;
            *reinterpret_cast<float4*>(&Bs[nxt][bRow + 8][bCol]) = b1;
            __syncthreads();   // next-buffer stores visible; cur free for reuse
        }
        cur = nxt;
    }

    // unpack accumulators and run epilogue
    float acc[GTM][GTN];
#pragma unroll
    for (int i = 0; i < GTM; i++)
#pragma unroll
        for (int j = 0; j < GTN / 2; j++)
            unpack_f32x2(acc[i][2 * j], acc[i][2 * j + 1], acc2[i][j]);

#pragma unroll
    for (int i = 0; i < GTM; i++) {
        int row = rowBase + ty * GTM + i;
#pragma unroll
        for (int j = 0; j < GTN; j++) {
            int col = colBase + tx * GTN + j;
            float v = acc[i][j];
            if (EPI == 0) {
                v += bias[col];
            } else if (EPI == 1) {
                v += bias[col];
                float a = extra[col];
                v = (v >= 0.0f) ? v : a * v;
            } else if (EPI == 2) {
                v += bias[col] + extra[(size_t)row * ldc + col];
            }
            C[(size_t)row * ldc + col] = v;
        }
    }
}

// ------- batched QK^T with mask+scale, double-buffered + FFMA2 --------------
constexpr int QBM = 64, QBN = 64, QBK = 16;

__global__ __launch_bounds__(256)
void qk_kernel(const float* __restrict__ Q, const float* __restrict__ Kt,
               const int* __restrict__ adj, float* __restrict__ S) {
    const int z = blockIdx.z;
    const int b = z / NH_, h = z % NH_;
    const float* Qp = Q + (size_t)b * N_ * H_ + (size_t)h * DH_;
    const float* Kp = Kt + (size_t)b * N_ * H_ + (size_t)h * DH_;
    const int* ap = adj + (size_t)b * N_ * N_;
    float* Sp = S + (size_t)z * N_ * N_;

    __shared__ alignas(16) float Qs[2][QBK][QBM];
    __shared__ alignas(16) float Ks[2][QBK][QBN];
    const int tid = threadIdx.x;
    const int rowBase = blockIdx.y * QBM;
    const int colBase = blockIdx.x * QBN;
    const int lRow = tid >> 2;           // 0..63
    const int lCol = (tid & 3) * 4;      // 0,4,8,12
    const int tx = tid % 16, ty = tid / 16;

    u64 acc2[4][2];
#pragma unroll
    for (int i = 0; i < 4; i++)
#pragma unroll
        for (int j = 0; j < 2; j++) acc2[i][j] = 0ull;

    // prologue: stage tile 0 into buffer 0
    {
        float4 q4 = *reinterpret_cast<const float4*>(Qp + (size_t)(rowBase + lRow) * H_ + lCol);
        float4 k4 = *reinterpret_cast<const float4*>(Kp + (size_t)(colBase + lRow) * H_ + lCol);
        Qs[0][lCol + 0][lRow] = q4.x;
        Qs[0][lCol + 1][lRow] = q4.y;
        Qs[0][lCol + 2][lRow] = q4.z;
        Qs[0][lCol + 3][lRow] = q4.w;
        Ks[0][lCol + 0][lRow] = k4.x;
        Ks[0][lCol + 1][lRow] = k4.y;
        Ks[0][lCol + 2][lRow] = k4.z;
        Ks[0][lCol + 3][lRow] = k4.w;
    }
    __syncthreads();

    int cur = 0;
    for (int k0 = 0; k0 < DH_; k0 += QBK) {
        const int nxt = cur ^ 1;
        const bool hasNext = (k0 + QBK) < DH_;

        float4 q4, k4;
        if (hasNext) {
            q4 = *reinterpret_cast<const float4*>(
                Qp + (size_t)(rowBase + lRow) * H_ + k0 + QBK + lCol);
            k4 = *reinterpret_cast<const float4*>(
                Kp + (size_t)(colBase + lRow) * H_ + k0 + QBK + lCol);
        }

#pragma unroll
        for (int k = 0; k < QBK; k++) {
            float4 rav = *reinterpret_cast<const float4*>(&Qs[cur][k][ty * 4]);
            const u64* rbp = reinterpret_cast<const u64*>(&Ks[cur][k][tx * 4]);
            u64 rb2[2] = {rbp[0], rbp[1]};
            float ra[4] = {rav.x, rav.y, rav.z, rav.w};
#pragma unroll
            for (int i = 0; i < 4; i++) {
                u64 a2 = dup_f32(ra[i]);
#pragma unroll
                for (int j = 0; j < 2; j++) ffma2(acc2[i][j], a2, rb2[j]);
            }
        }

        if (hasNext) {
            Qs[nxt][lCol + 0][lRow] = q4.x;
            Qs[nxt][lCol + 1][lRow] = q4.y;
            Qs[nxt][lCol + 2][lRow] = q4.z;
            Qs[nxt][lCol + 3][lRow] = q4.w;
            Ks[nxt][lCol + 0][lRow] = k4.x;
            Ks[nxt][lCol + 1][lRow] = k4.y;
            Ks[nxt][lCol + 2][lRow] = k4.z;
            Ks[nxt][lCol + 3][lRow] = k4.w;
            __syncthreads();
        }
        cur = nxt;
    }

    float acc[4][4];
#pragma unroll
    for (int i = 0; i < 4; i++)
#pragma unroll
        for (int j = 0; j < 2; j++)
            unpack_f32x2(acc[i][2 * j], acc[i][2 * j + 1], acc2[i][j]);

    const float scale = 0.08838834764831845f;  // 1/sqrt(128)
#pragma unroll
    for (int i = 0; i < 4; i++) {
        int row = rowBase + ty * 4 + i;
        // 4 adjacent cols -> one int4 mask load, one float4 store
        const int4 m4 = *reinterpret_cast<const int4*>(&ap[(size_t)row * N_ + colBase + tx * 4]);
        const int mm[4] = {m4.x, m4.y, m4.z, m4.w};
        float4 outv;
        float* ov = reinterpret_cast<float*>(&outv);
#pragma unroll
        for (int j = 0; j < 4; j++) {
            float v = acc[i][j] * scale;
            if (mm[j] == 0) v = -1.0e9f;
            ov[j] = v;
        }
        *reinterpret_cast<float4*>(&Sp[(size_t)row * N_ + colBase + tx * 4]) = outv;
    }
}

// ---- row softmax (row length N=2048, 256 thr, 8/thread, float4 I/O) --------
__global__ __launch_bounds__(256)
void softmax_kernel(float* __restrict__ S) {
    float* p = S + (size_t)blockIdx.x * N_;
    const int tid = threadIdx.x;
    __shared__ float sh[8];

    // each thread owns 8 contiguous floats = 2 float4
    float4 v0 = reinterpret_cast<const float4*>(p)[tid * 2];
    float4 v1 = reinterpret_cast<const float4*>(p)[tid * 2 + 1];
    float vals[8] = {v0.x, v0.y, v0.z, v0.w, v1.x, v1.y, v1.z, v1.w};

    float m = -1.0e30f;
#pragma unroll
    for (int i = 0; i < 8; i++) m = fmaxf(m, vals[i]);
#pragma unroll
    for (int o = 16; o > 0; o >>= 1) m = fmaxf(m, __shfl_xor_sync(0xffffffffu, m, o));
    if ((tid & 31) == 0) sh[tid >> 5] = m;
    __syncthreads();
    m = sh[0];
#pragma unroll
    for (int i = 1; i < 8; i++) m = fmaxf(m, sh[i]);
    __syncthreads();

    float sum = 0.0f;
#pragma unroll
    for (int i = 0; i < 8; i++) {
        vals[i] = __expf(vals[i] - m);
        sum += vals[i];
    }
#pragma unroll
    for (int o = 16; o > 0; o >>= 1) sum += __shfl_xor_sync(0xffffffffu, sum, o);
    if ((tid & 31) == 0) sh[tid >> 5] = sum;
    __syncthreads();
    sum = 0.0f;
#pragma unroll
    for (int i = 0; i < 8; i++) sum += sh[i];
    float inv = 1.0f / sum;

    float4 w0 = make_float4(vals[0] * inv, vals[1] * inv, vals[2] * inv, vals[3] * inv);
    float4 w1 = make_float4(vals[4] * inv, vals[5] * inv, vals[6] * inv, vals[7] * inv);
    reinterpret_cast<float4*>(p)[tid * 2]     = w0;
    reinterpret_cast<float4*>(p)[tid * 2 + 1] = w1;
}

// -------------------- LayerNorm over H=512 (256 thr, 2/thread) --------------
__global__ __launch_bounds__(256)
void ln_kernel(const float* __restrict__ X, float* __restrict__ Y,
               const float* __restrict__ g, const float* __restrict__ b) {
    const float* x = X + (size_t)blockIdx.x * H_;
    float* y = Y + (size_t)blockIdx.x * H_;
    const int tid = threadIdx.x;
    __shared__ float sh[8];

    float v0 = x[tid], v1 = x[tid + 256];
    float s = v0 + v1;
    float s2 = v0 * v0 + v1 * v1;
#pragma unroll
    for (int o = 16; o > 0; o >>= 1) {
        s  += __shfl_xor_sync(0xffffffffu, s, o);
        s2 += __shfl_xor_sync(0xffffffffu, s2, o);
    }
    if ((tid & 31) == 0) sh[tid >> 5] = s;
    __syncthreads();
    float tot = 0.0f;
#pragma unroll
    for (int i = 0; i < 8; i++) tot += sh[i];
    __syncthreads();
    if ((tid & 31) == 0) sh[tid >> 5] = s2;
    __syncthreads();
    float tot2 = 0.0f;
#pragma unroll
    for (int i = 0; i < 8; i++) tot2 += sh[i];

    float mean = tot * (1.0f / H_);
    float var = tot2 * (1.0f / H_) - mean * mean;
    float inv = rsqrtf(var + 1.0e-5f);
    y[tid]       = (v0 - mean) * inv * g[tid] + b[tid];
    y[tid + 256] = (v1 - mean) * inv * g[tid + 256] + b[tid + 256];
}

// -------------------- output assembly ---------------------------------------
__global__ void copy_gents_kernel(const float* __restrict__ x, float* __restrict__ out) {
    size_t i = (size_t)blockIdx.x * blockDim.x + threadIdx.x;
    if (i < (size_t)B_ * N_ * H_ / 4) {
        reinterpret_cast<float4*>(out + (size_t)B_ * H_)[i] =
            reinterpret_cast<const float4*>(x)[i];
    }
}

__global__ void finalize_head_kernel(const float* __restrict__ x, float* __restrict__ out) {
    int idx = blockIdx.x * blockDim.x + threadIdx.x;
    if (idx < B_ * H_) {           // glob = x[:, entlen=E_]
        int b = idx / H_, c = idx % H_;
        out[idx] = x[((size_t)b * N_ + E_) * H_ + c];
    }
    if (idx < B_ * N_) {           // emask: arange(N) <= N -> all True
        out[(size_t)B_ * H_ + (size_t)B_ * N_ * H_ + idx] = 1.0f;
    }
}

// -------------------- host launcher -----------------------------------------
extern "C" void kernel_launch(void* const* d_in, const int* in_sizes, int n_in,
                              void* d_out, int out_size) {
    int i = 0;
    const int*   adjs  = (const int*)d_in[i++];
    const int*   rels  = (const int*)d_in[i++];
    const float* vents = (const float*)d_in[i++];
    if (i < n_in && in_sizes[i] == 1) i++;   // entlen scalar, value fixed at E_
    const float* renc = (const float*)d_in[i++];
    const float* Wq = (const float*)d_in[i++];
    const float* Wk = (const float*)d_in[i++];
    const float* Wv = (const float*)d_in[i++];
    const float* Wo = (const float*)d_in[i++];
    const float* W1 = (const float*)d_in[i++];
    const float* W2 = (const float*)d_in[i++];
    const float* bq = (const float*)d_in[i++];
    const float* bk = (const float*)d_in[i++];
    const float* bv = (const float*)d_in[i++];
    const float* bo = (const float*)d_in[i++];
    const float* b1 = (const float*)d_in[i++];
    const float* b2 = (const float*)d_in[i++];
    const float* ln1g = (const float*)d_in[i++];
    const float* ln1b = (const float*)d_in[i++];
    const float* ln2g = (const float*)d_in[i++];
    const float* ln2b = (const float*)d_in[i++];
    const float* prelu = (const float*)d_in[i++];

    float *x, *q, *k, *v, *o, *t, *y, *h, *s;
    cudaGetSymbolAddress((void**)&x, g_x);
    cudaGetSymbolAddress((void**)&q, g_q);
    cudaGetSymbolAddress((void**)&k, g_k);
    cudaGetSymbolAddress((void**)&v, g_v);
    cudaGetSymbolAddress((void**)&o, g_o);
    cudaGetSymbolAddress((void**)&t, g_t);
    cudaGetSymbolAddress((void**)&y, g_y);
    cudaGetSymbolAddress((void**)&h, g_h);
    cudaGetSymbolAddress((void**)&s, g_s);

    const int M = B_ * N_;   // 8192

    {
        size_t tot = (size_t)B_ * N_ * H_;
        build_x_kernel<<<(unsigned)((tot + 255) / 256), 256>>>(vents, rels, renc, x);
    }

    for (int j = 0; j < P_; j++) {
        size_t wo  = (size_t)j * H_ * H_;
        size_t w1o = (size_t)j * H_ * FF_;
        size_t w2o = (size_t)j * FF_ * H_;

        dim3 gHH(H_ / GBN, M / GBM);              // (4, 64)
        dim3 gQKV(H_ / GBN, M / GBM, 3);          // (4, 64, 3) fused QKV
        dim3 gFF(FF_ / GBN, M / GBM);             // (16, 64)

        QKVArgs qa;
        qa.W[0] = Wq + wo;  qa.W[1] = Wk + wo;  qa.W[2] = Wv + wo;
        qa.bias[0] = bq + j * H_;  qa.bias[1] = bk + j * H_;  qa.bias[2] = bv + j * H_;
        qa.C[0] = q;  qa.C[1] = k;  qa.C[2] = v;

        sgemm_nn<0, 1><<<gQKV, 256>>>(x, H_, nullptr, H_, nullptr, H_, H_,
                                      nullptr, nullptr, qa);

        dim3 gqk(N_ / QBN, N_ / QBM, B_ * NH_);       // (32, 32, 16)
        qk_kernel<<<gqk, 256>>>(q, k, adjs, s);

        softmax_kernel<<<B_ * NH_ * N_, 256>>>(s);

        dim3 gav(DH_ / GBN, N_ / GBM, B_ * NH_);      // (1, 16, 16)
        sgemm_nn<3, 2><<<gav, 256>>>(s, N_, v, H_, o, H_, N_, nullptr, nullptr);

        sgemm_nn<0, 0><<<gHH, 256>>>(o, H_, Wo + wo, H_, y, H_, H_, bo + j * H_, nullptr);
        ln_kernel<<<B_ * N_, 256>>>(y, t, ln1g + j * H_, ln1b + j * H_);

        sgemm_nn<1, 0><<<gFF, 256>>>(t, H_, W1 + w1o, FF_, h, FF_, H_,
                                     b1 + j * FF_, prelu + j * FF_);
        sgemm_nn<2, 0><<<gHH, 256>>>(h, FF_, W2 + w2o, H_, y, H_, FF_,
                                     b2 + j * H_, t);
        ln_kernel<<<B_ * N_, 256>>>(y, x, ln2g + j * H_, ln2b + j * H_);
    }

    {
        size_t tot4 = (size_t)B_ * N_ * H_ / 4;
        copy_gents_kernel<<<(unsigned)((tot4 + 255) / 256), 256>>>(x, (float*)d_out);
        finalize_head_kernel<<<(B_ * N_ + 255) / 256, 256>>>(x, (float*)d_out);
    }
}

// round 7
// speedup vs baseline: 2.5034x; 2.5034x over previous
#include <cuda_runtime.h>
#include <cstdint>
#include <cstddef>

// Problem constants (fixed by setup_inputs)
constexpr int B_  = 4;
constexpr int N_  = 2048;
constexpr int E_  = 1600;
constexpr int R_  = 448;
constexpr int H_  = 512;
constexpr int NH_ = 4;
constexpr int DH_ = 128;
constexpr int FF_ = 2048;   // 4*H
constexpr int P_  = 2;

typedef unsigned int uint32;

// ---- tf32 helpers ----------------------------------------------------------
__device__ __forceinline__ uint32 f2tf32(float x) {
    uint32 r;
    asm("cvt.rna.tf32.f32 %0, %1;" : "=r"(r) : "f"(x));
    return r;
}
__device__ __forceinline__ void mma_tf32(float* c, const uint32* a, const uint32* b) {
    asm volatile(
        "mma.sync.aligned.m16n8k8.row.col.f32.tf32.tf32.f32 "
        "{%0,%1,%2,%3}, {%4,%5,%6,%7}, {%8,%9}, {%0,%1,%2,%3};"
        : "+f"(c[0]), "+f"(c[1]), "+f"(c[2]), "+f"(c[3])
        : "r"(a[0]), "r"(a[1]), "r"(a[2]), "r"(a[3]), "r"(b[0]), "r"(b[1]));
}

// -------------------- scratch (__device__ globals; no allocs) ---------------
__device__ float g_x[(size_t)B_ * N_ * H_];
__device__ float g_q[(size_t)B_ * N_ * H_];
__device__ float g_k[(size_t)B_ * N_ * H_];
__device__ float g_v[(size_t)B_ * N_ * H_];
__device__ float g_o[(size_t)B_ * N_ * H_];
__device__ float g_t[(size_t)B_ * N_ * H_];
__device__ float g_y[(size_t)B_ * N_ * H_];
__device__ float g_h[(size_t)B_ * N_ * FF_];
__device__ float g_s[(size_t)B_ * NH_ * N_ * N_];   // 256 MB attention scores

// pointer bundle for fused-QKV launch (passed by value)
struct QKVArgs {
    const float* W[3];
    const float* bias[3];
    float* C[3];
};

// -------------------- build x = concat(vents, renc_w[rels]) ----------------
__global__ void build_x_kernel(const float* __restrict__ vents,
                               const int* __restrict__ rels,
                               const float* __restrict__ renc,
                               float* __restrict__ x) {
    size_t idx = (size_t)blockIdx.x * blockDim.x + threadIdx.x;
    if (idx >= (size_t)B_ * N_ * H_) return;
    int c = (int)(idx % H_);
    size_t t = idx / H_;
    int n = (int)(t % N_);
    int b = (int)(t / N_);
    float val;
    if (n < E_) {
        val = vents[((size_t)b * E_ + n) * H_ + c];
    } else {
        int rel = rels[b * R_ + (n - E_)];
        val = renc[(size_t)rel * H_ + c];
    }
    x[idx] = val;
}

// ------- 128x128x16 TF32 tensor-core GEMM (NN), double-buffered -------------
// EPI: 0 = +bias ; 1 = +bias then PReLU(alpha=extra[col]) ;
//      2 = +bias + extra[row*ldc+col] (residual) ; 3 = plain
// BMODE: 0 = none ; 1 = fused QKV ; 2 = AV batch
constexpr int GBM = 128, GBN = 128, GBK = 16;
constexpr int ASTR = GBM + 8;   // 136-word rows -> conflict-free frag loads
constexpr int BSTR = GBN + 8;

template <int EPI, int BMODE>
__global__ __launch_bounds__(256)
void gemm_tc(const float* __restrict__ A, int lda,
             const float* __restrict__ Bm, int ldb,
             float* __restrict__ C, int ldc, int K,
             const float* __restrict__ bias,
             const float* __restrict__ extra,
             QKVArgs qkv = {}) {
    if (BMODE == 1) {
        int z = blockIdx.z;          // 0=Q, 1=K, 2=V
        Bm   = qkv.W[z];
        bias = qkv.bias[z];
        C    = qkv.C[z];
    } else if (BMODE == 2) {
        int z = blockIdx.z;
        A += (size_t)z * N_ * N_;
        size_t off = (size_t)(z / NH_) * N_ * H_ + (size_t)(z % NH_) * DH_;
        Bm += off;
        C  += off;
    }
    __shared__ uint32 As[2][GBK][ASTR];   // As[buf][k][m], tf32 bits
    __shared__ uint32 Bs[2][GBK][BSTR];   // Bs[buf][k][n]
    const int tid  = threadIdx.x;
    const int lane = tid & 31;
    const int wid  = tid >> 5;
    const int g  = lane >> 2;     // 0..7
    const int tg = lane & 3;      // 0..3
    const int mwarp = (wid >> 2) * 64;   // 2 warps in M
    const int nwarp = (wid & 3) * 32;    // 4 warps in N
    const int rowBase = blockIdx.y * GBM;
    const int colBase = blockIdx.x * GBN;

    // A loaders: 128x16 tile, 512 float4, 2/thread
    const int aRow = tid >> 2;            // 0..63 (+64 second pass)
    const int aCol = (tid & 3) * 4;       // 0,4,8,12
    // B loaders: 16x128 tile, 512 float4, 2/thread
    const int bRow = tid >> 5;            // 0..7 (+8 second pass)
    const int bCol = (tid & 31) * 4;      // 0..124

    const float* Aptr0 = A + (size_t)(rowBase + aRow) * lda + aCol;
    const float* Aptr1 = Aptr0 + (size_t)64 * lda;
    const float* Bptr0 = Bm + (size_t)bRow * ldb + colBase + bCol;
    const float* Bptr1 = Bptr0 + (size_t)8 * ldb;

    float c[4][4][4];   // [mf][nf][4]
#pragma unroll
    for (int mf = 0; mf < 4; mf++)
#pragma unroll
        for (int nf = 0; nf < 4; nf++)
#pragma unroll
            for (int e = 0; e < 4; e++) c[mf][nf][e] = 0.0f;

    // prologue: stage tile 0 into buffer 0 (convert to tf32)
    {
        float4 a0 = *reinterpret_cast<const float4*>(Aptr0);
        float4 a1 = *reinterpret_cast<const float4*>(Aptr1);
        float4 b0 = *reinterpret_cast<const float4*>(Bptr0);
        float4 b1 = *reinterpret_cast<const float4*>(Bptr1);
        As[0][aCol + 0][aRow]      = f2tf32(a0.x);
        As[0][aCol + 1][aRow]      = f2tf32(a0.y);
        As[0][aCol + 2][aRow]      = f2tf32(a0.z);
        As[0][aCol + 3][aRow]      = f2tf32(a0.w);
        As[0][aCol + 0][aRow + 64] = f2tf32(a1.x);
        As[0][aCol + 1][aRow + 64] = f2tf32(a1.y);
        As[0][aCol + 2][aRow + 64] = f2tf32(a1.z);
        As[0][aCol + 3][aRow + 64] = f2tf32(a1.w);
        uint32* bp0 = &Bs[0][bRow][bCol];
        bp0[0] = f2tf32(b0.x); bp0[1] = f2tf32(b0.y);
        bp0[2] = f2tf32(b0.z); bp0[3] = f2tf32(b0.w);
        uint32* bp1 = &Bs[0][bRow + 8][bCol];
        bp1[0] = f2tf32(b1.x); bp1[1] = f2tf32(b1.y);
        bp1[2] = f2tf32(b1.z); bp1[3] = f2tf32(b1.w);
    }
    __syncthreads();

    int cur = 0;
    for (int k0 = 0; k0 < K; k0 += GBK) {
        const int nxt = cur ^ 1;
        const bool hasNext = (k0 + GBK) < K;

        float4 a0, a1, b0, b1;
        if (hasNext) {
            a0 = *reinterpret_cast<const float4*>(Aptr0 + k0 + GBK);
            a1 = *reinterpret_cast<const float4*>(Aptr1 + k0 + GBK);
            b0 = *reinterpret_cast<const float4*>(Bptr0 + (size_t)(k0 + GBK) * ldb);
            b1 = *reinterpret_cast<const float4*>(Bptr1 + (size_t)(k0 + GBK) * ldb);
        }

        // 2 k-steps of 8; 16 MMAs per warp per k-step
#pragma unroll
        for (int ks = 0; ks < 2; ks++) {
            const int kb = ks * 8;
            uint32 af[4][4];
#pragma unroll
            for (int mf = 0; mf < 4; mf++) {
                int row = mwarp + mf * 16 + g;
                af[mf][0] = As[cur][kb + tg][row];
                af[mf][1] = As[cur][kb + tg][row + 8];
                af[mf][2] = As[cur][kb + tg + 4][row];
                af[mf][3] = As[cur][kb + tg + 4][row + 8];
            }
            uint32 bf[4][2];
#pragma unroll
            for (int nf = 0; nf < 4; nf++) {
                int coln = nwarp + nf * 8 + g;
                bf[nf][0] = Bs[cur][kb + tg][coln];
                bf[nf][1] = Bs[cur][kb + tg + 4][coln];
            }
#pragma unroll
            for (int mf = 0; mf < 4; mf++)
#pragma unroll
                for (int nf = 0; nf < 4; nf++)
                    mma_tf32(c[mf][nf], af[mf], bf[nf]);
        }

        if (hasNext) {
            As[nxt][aCol + 0][aRow]      = f2tf32(a0.x);
            As[nxt][aCol + 1][aRow]      = f2tf32(a0.y);
            As[nxt][aCol + 2][aRow]      = f2tf32(a0.z);
            As[nxt][aCol + 3][aRow]      = f2tf32(a0.w);
            As[nxt][aCol + 0][aRow + 64] = f2tf32(a1.x);
            As[nxt][aCol + 1][aRow + 64] = f2tf32(a1.y);
            As[nxt][aCol + 2][aRow + 64] = f2tf32(a1.z);
            As[nxt][aCol + 3][aRow + 64] = f2tf32(a1.w);
            uint32* bp0 = &Bs[nxt][bRow][bCol];
            bp0[0] = f2tf32(b0.x); bp0[1] = f2tf32(b0.y);
            bp0[2] = f2tf32(b0.z); bp0[3] = f2tf32(b0.w);
            uint32* bp1 = &Bs[nxt][bRow + 8][bCol];
            bp1[0] = f2tf32(b1.x); bp1[1] = f2tf32(b1.y);
            bp1[2] = f2tf32(b1.z); bp1[3] = f2tf32(b1.w);
            __syncthreads();
        }
        cur = nxt;
    }

    // epilogue: fragment (row, col) mapping; pairs are contiguous cols
#pragma unroll
    for (int mf = 0; mf < 4; mf++) {
#pragma unroll
        for (int nf = 0; nf < 4; nf++) {
            const float* cf = c[mf][nf];
            int row0 = rowBase + mwarp + mf * 16 + g;
            int col  = colBase + nwarp + nf * 8 + 2 * tg;
#pragma unroll
            for (int half = 0; half < 2; half++) {
                int row = row0 + half * 8;
                float v0 = cf[half * 2 + 0];
                float v1 = cf[half * 2 + 1];
                if (EPI == 0) {
                    float2 bb = *reinterpret_cast<const float2*>(&bias[col]);
                    v0 += bb.x; v1 += bb.y;
                } else if (EPI == 1) {
                    float2 bb = *reinterpret_cast<const float2*>(&bias[col]);
                    float2 aa = *reinterpret_cast<const float2*>(&extra[col]);
                    v0 += bb.x; v1 += bb.y;
                    v0 = (v0 >= 0.0f) ? v0 : aa.x * v0;
                    v1 = (v1 >= 0.0f) ? v1 : aa.y * v1;
                } else if (EPI == 2) {
                    float2 bb = *reinterpret_cast<const float2*>(&bias[col]);
                    float2 rr = *reinterpret_cast<const float2*>(&extra[(size_t)row * ldc + col]);
                    v0 += bb.x + rr.x; v1 += bb.y + rr.y;
                }
                *reinterpret_cast<float2*>(&C[(size_t)row * ldc + col]) =
                    make_float2(v0, v1);
            }
        }
    }
}

// ------- batched QK^T (NT) with mask+scale, TF32 tensor cores ---------------
__global__ __launch_bounds__(256)
void qk_tc(const float* __restrict__ Q, const float* __restrict__ Kt,
           const int* __restrict__ adj, float* __restrict__ S) {
    const int z = blockIdx.z;
    const int b = z / NH_, h = z % NH_;
    const float* Qp = Q + (size_t)b * N_ * H_ + (size_t)h * DH_;
    const float* Kp = Kt + (size_t)b * N_ * H_ + (size_t)h * DH_;
    const int* ap = adj + (size_t)b * N_ * N_;
    float* Sp = S + (size_t)z * N_ * N_;

    __shared__ uint32 As[2][GBK][ASTR];   // Q tile  [k][m]
    __shared__ uint32 Bs[2][GBK][BSTR];   // K^T tile [k][n]
    const int tid  = threadIdx.x;
    const int lane = tid & 31;
    const int wid  = tid >> 5;
    const int g  = lane >> 2;
    const int tg = lane & 3;
    const int mwarp = (wid >> 2) * 64;
    const int nwarp = (wid & 3) * 32;
    const int rowBase = blockIdx.y * GBM;
    const int colBase = blockIdx.x * GBN;

    const int aRow = tid >> 2;
    const int aCol = (tid & 3) * 4;

    const float* Aptr0 = Qp + (size_t)(rowBase + aRow) * H_ + aCol;
    const float* Aptr1 = Aptr0 + (size_t)64 * H_;
    // B loader: K rows (n index) transposed into Bs[k][n]
    const float* Bptr0 = Kp + (size_t)(colBase + aRow) * H_ + aCol;
    const float* Bptr1 = Bptr0 + (size_t)64 * H_;

    float c[4][4][4];
#pragma unroll
    for (int mf = 0; mf < 4; mf++)
#pragma unroll
        for (int nf = 0; nf < 4; nf++)
#pragma unroll
            for (int e = 0; e < 4; e++) c[mf][nf][e] = 0.0f;

    {
        float4 a0 = *reinterpret_cast<const float4*>(Aptr0);
        float4 a1 = *reinterpret_cast<const float4*>(Aptr1);
        float4 b0 = *reinterpret_cast<const float4*>(Bptr0);
        float4 b1 = *reinterpret_cast<const float4*>(Bptr1);
        As[0][aCol + 0][aRow]      = f2tf32(a0.x);
        As[0][aCol + 1][aRow]      = f2tf32(a0.y);
        As[0][aCol + 2][aRow]      = f2tf32(a0.z);
        As[0][aCol + 3][aRow]      = f2tf32(a0.w);
        As[0][aCol + 0][aRow + 64] = f2tf32(a1.x);
        As[0][aCol + 1][aRow + 64] = f2tf32(a1.y);
        As[0][aCol + 2][aRow + 64] = f2tf32(a1.z);
        As[0][aCol + 3][aRow + 64] = f2tf32(a1.w);
        Bs[0][aCol + 0][aRow]      = f2tf32(b0.x);
        Bs[0][aCol + 1][aRow]      = f2tf32(b0.y);
        Bs[0][aCol + 2][aRow]      = f2tf32(b0.z);
        Bs[0][aCol + 3][aRow]      = f2tf32(b0.w);
        Bs[0][aCol + 0][aRow + 64] = f2tf32(b1.x);
        Bs[0][aCol + 1][aRow + 64] = f2tf32(b1.y);
        Bs[0][aCol + 2][aRow + 64] = f2tf32(b1.z);
        Bs[0][aCol + 3][aRow + 64] = f2tf32(b1.w);
    }
    __syncthreads();

    int cur = 0;
    for (int k0 = 0; k0 < DH_; k0 += GBK) {
        const int nxt = cur ^ 1;
        const bool hasNext = (k0 + GBK) < DH_;

        float4 a0, a1, b0, b1;
        if (hasNext) {
            a0 = *reinterpret_cast<const float4*>(Aptr0 + k0 + GBK);
            a1 = *reinterpret_cast<const float4*>(Aptr1 + k0 + GBK);
            b0 = *reinterpret_cast<const float4*>(Bptr0 + k0 + GBK);
            b1 = *reinterpret_cast<const float4*>(Bptr1 + k0 + GBK);
        }

#pragma unroll
        for (int ks = 0; ks < 2; ks++) {
            const int kb = ks * 8;
            uint32 af[4][4];
#pragma unroll
            for (int mf = 0; mf < 4; mf++) {
                int row = mwarp + mf * 16 + g;
                af[mf][0] = As[cur][kb + tg][row];
                af[mf][1] = As[cur][kb + tg][row + 8];
                af[mf][2] = As[cur][kb + tg + 4][row];
                af[mf][3] = As[cur][kb + tg + 4][row + 8];
            }
            uint32 bf[4][2];
#pragma unroll
            for (int nf = 0; nf < 4; nf++) {
                int coln = nwarp + nf * 8 + g;
                bf[nf][0] = Bs[cur][kb + tg][coln];
                bf[nf][1] = Bs[cur][kb + tg + 4][coln];
            }
#pragma unroll
            for (int mf = 0; mf < 4; mf++)
#pragma unroll
                for (int nf = 0; nf < 4; nf++)
                    mma_tf32(c[mf][nf], af[mf], bf[nf]);
        }

        if (hasNext) {
            As[nxt][aCol + 0][aRow]      = f2tf32(a0.x);
            As[nxt][aCol + 1][aRow]      = f2tf32(a0.y);
            As[nxt][aCol + 2][aRow]      = f2tf32(a0.z);
            As[nxt][aCol + 3][aRow]      = f2tf32(a0.w);
            As[nxt][aCol + 0][aRow + 64] = f2tf32(a1.x);
            As[nxt][aCol + 1][aRow + 64] = f2tf32(a1.y);
            As[nxt][aCol + 2][aRow + 64] = f2tf32(a1.z);
            As[nxt][aCol + 3][aRow + 64] = f2tf32(a1.w);
            Bs[nxt][aCol + 0][aRow]      = f2tf32(b0.x);
            Bs[nxt][aCol + 1][aRow]      = f2tf32(b0.y);
            Bs[nxt][aCol + 2][aRow]      = f2tf32(b0.z);
            Bs[nxt][aCol + 3][aRow]      = f2tf32(b0.w);
            Bs[nxt][aCol + 0][aRow + 64] = f2tf32(b1.x);
            Bs[nxt][aCol + 1][aRow + 64] = f2tf32(b1.y);
            Bs[nxt][aCol + 2][aRow + 64] = f2tf32(b1.z);
            Bs[nxt][aCol + 3][aRow + 64] = f2tf32(b1.w);
            __syncthreads();
        }
        cur = nxt;
    }

    const float scale = 0.08838834764831845f;  // 1/sqrt(128)
#pragma unroll
    for (int mf = 0; mf < 4; mf++) {
#pragma unroll
        for (int nf = 0; nf < 4; nf++) {
            const float* cf = c[mf][nf];
            int row0 = rowBase + mwarp + mf * 16 + g;
            int col  = colBase + nwarp + nf * 8 + 2 * tg;
#pragma unroll
            for (int half = 0; half < 2; half++) {
                int row = row0 + half * 8;
                int2 mm = *reinterpret_cast<const int2*>(&ap[(size_t)row * N_ + col]);
                float v0 = cf[half * 2 + 0] * scale;
                float v1 = cf[half * 2 + 1] * scale;
                if (mm.x == 0) v0 = -1.0e9f;
                if (mm.y == 0) v1 = -1.0e9f;
                *reinterpret_cast<float2*>(&Sp[(size_t)row * N_ + col]) =
                    make_float2(v0, v1);
            }
        }
    }
}

// ---- row softmax (row length N=2048, 256 thr, 8/thread, float4 I/O) --------
__global__ __launch_bounds__(256)
void softmax_kernel(float* __restrict__ S) {
    float* p = S + (size_t)blockIdx.x * N_;
    const int tid = threadIdx.x;
    __shared__ float sh[8];

    float4 v0 = reinterpret_cast<const float4*>(p)[tid * 2];
    float4 v1 = reinterpret_cast<const float4*>(p)[tid * 2 + 1];
    float vals[8] = {v0.x, v0.y, v0.z, v0.w, v1.x, v1.y, v1.z, v1.w};

    float m = -1.0e30f;
#pragma unroll
    for (int i = 0; i < 8; i++) m = fmaxf(m, vals[i]);
#pragma unroll
    for (int o = 16; o > 0; o >>= 1) m = fmaxf(m, __shfl_xor_sync(0xffffffffu, m, o));
    if ((tid & 31) == 0) sh[tid >> 5] = m;
    __syncthreads();
    m = sh[0];
#pragma unroll
    for (int i = 1; i < 8; i++) m = fmaxf(m, sh[i]);
    __syncthreads();

    float sum = 0.0f;
#pragma unroll
    for (int i = 0; i < 8; i++) {
        vals[i] = __expf(vals[i] - m);
        sum += vals[i];
    }
#pragma unroll
    for (int o = 16; o > 0; o >>= 1) sum += __shfl_xor_sync(0xffffffffu, sum, o);
    if ((tid & 31) == 0) sh[tid >> 5] = sum;
    __syncthreads();
    sum = 0.0f;
#pragma unroll
    for (int i = 0; i < 8; i++) sum += sh[i];
    float inv = 1.0f / sum;

    float4 w0 = make_float4(vals[0] * inv, vals[1] * inv, vals[2] * inv, vals[3] * inv);
    float4 w1 = make_float4(vals[4] * inv, vals[5] * inv, vals[6] * inv, vals[7] * inv);
    reinterpret_cast<float4*>(p)[tid * 2]     = w0;
    reinterpret_cast<float4*>(p)[tid * 2 + 1] = w1;
}

// -------------------- LayerNorm over H=512 (256 thr, 2/thread) --------------
__global__ __launch_bounds__(256)
void ln_kernel(const float* __restrict__ X, float* __restrict__ Y,
               const float* __restrict__ g, const float* __restrict__ b) {
    const float* x = X + (size_t)blockIdx.x * H_;
    float* y = Y + (size_t)blockIdx.x * H_;
    const int tid = threadIdx.x;
    __shared__ float sh[8];

    float v0 = x[tid], v1 = x[tid + 256];
    float s = v0 + v1;
    float s2 = v0 * v0 + v1 * v1;
#pragma unroll
    for (int o = 16; o > 0; o >>= 1) {
        s  += __shfl_xor_sync(0xffffffffu, s, o);
        s2 += __shfl_xor_sync(0xffffffffu, s2, o);
    }
    if ((tid & 31) == 0) sh[tid >> 5] = s;
    __syncthreads();
    float tot = 0.0f;
#pragma unroll
    for (int i = 0; i < 8; i++) tot += sh[i];
    __syncthreads();
    if ((tid & 31) == 0) sh[tid >> 5] = s2;
    __syncthreads();
    float tot2 = 0.0f;
#pragma unroll
    for (int i = 0; i < 8; i++) tot2 += sh[i];

    float mean = tot * (1.0f / H_);
    float var = tot2 * (1.0f / H_) - mean * mean;
    float inv = rsqrtf(var + 1.0e-5f);
    y[tid]       = (v0 - mean) * inv * g[tid] + b[tid];
    y[tid + 256] = (v1 - mean) * inv * g[tid + 256] + b[tid + 256];
}

// -------------------- output assembly ---------------------------------------
__global__ void copy_gents_kernel(const float* __restrict__ x, float* __restrict__ out) {
    size_t i = (size_t)blockIdx.x * blockDim.x + threadIdx.x;
    if (i < (size_t)B_ * N_ * H_ / 4) {
        reinterpret_cast<float4*>(out + (size_t)B_ * H_)[i] =
            reinterpret_cast<const float4*>(x)[i];
    }
}

__global__ void finalize_head_kernel(const float* __restrict__ x, float* __restrict__ out) {
    int idx = blockIdx.x * blockDim.x + threadIdx.x;
    if (idx < B_ * H_) {           // glob = x[:, entlen=E_]
        int b = idx / H_, c = idx % H_;
        out[idx] = x[((size_t)b * N_ + E_) * H_ + c];
    }
    if (idx < B_ * N_) {           // emask: arange(N) <= N -> all True
        out[(size_t)B_ * H_ + (size_t)B_ * N_ * H_ + idx] = 1.0f;
    }
}

// -------------------- host launcher -----------------------------------------
extern "C" void kernel_launch(void* const* d_in, const int* in_sizes, int n_in,
                              void* d_out, int out_size) {
    int i = 0;
    const int*   adjs  = (const int*)d_in[i++];
    const int*   rels  = (const int*)d_in[i++];
    const float* vents = (const float*)d_in[i++];
    if (i < n_in && in_sizes[i] == 1) i++;   // entlen scalar, value fixed at E_
    const float* renc = (const float*)d_in[i++];
    const float* Wq = (const float*)d_in[i++];
    const float* Wk = (const float*)d_in[i++];
    const float* Wv = (const float*)d_in[i++];
    const float* Wo = (const float*)d_in[i++];
    const float* W1 = (const float*)d_in[i++];
    const float* W2 = (const float*)d_in[i++];
    const float* bq = (const float*)d_in[i++];
    const float* bk = (const float*)d_in[i++];
    const float* bv = (const float*)d_in[i++];
    const float* bo = (const float*)d_in[i++];
    const float* b1 = (const float*)d_in[i++];
    const float* b2 = (const float*)d_in[i++];
    const float* ln1g = (const float*)d_in[i++];
    const float* ln1b = (const float*)d_in[i++];
    const float* ln2g = (const float*)d_in[i++];
    const float* ln2b = (const float*)d_in[i++];
    const float* prelu = (const float*)d_in[i++];

    float *x, *q, *k, *v, *o, *t, *y, *h, *s;
    cudaGetSymbolAddress((void**)&x, g_x);
    cudaGetSymbolAddress((void**)&q, g_q);
    cudaGetSymbolAddress((void**)&k, g_k);
    cudaGetSymbolAddress((void**)&v, g_v);
    cudaGetSymbolAddress((void**)&o, g_o);
    cudaGetSymbolAddress((void**)&t, g_t);
    cudaGetSymbolAddress((void**)&y, g_y);
    cudaGetSymbolAddress((void**)&h, g_h);
    cudaGetSymbolAddress((void**)&s, g_s);

    const int M = B_ * N_;   // 8192

    {
        size_t tot = (size_t)B_ * N_ * H_;
        build_x_kernel<<<(unsigned)((tot + 255) / 256), 256>>>(vents, rels, renc, x);
    }

    for (int j = 0; j < P_; j++) {
        size_t wo  = (size_t)j * H_ * H_;
        size_t w1o = (size_t)j * H_ * FF_;
        size_t w2o = (size_t)j * FF_ * H_;

        dim3 gHH(H_ / GBN, M / GBM);              // (4, 64)
        dim3 gQKV(H_ / GBN, M / GBM, 3);          // (4, 64, 3) fused QKV
        dim3 gFF(FF_ / GBN, M / GBM);             // (16, 64)

        QKVArgs qa;
        qa.W[0] = Wq + wo;  qa.W[1] = Wk + wo;  qa.W[2] = Wv + wo;
        qa.bias[0] = bq + j * H_;  qa.bias[1] = bk + j * H_;  qa.bias[2] = bv + j * H_;
        qa.C[0] = q;  qa.C[1] = k;  qa.C[2] = v;

        gemm_tc<0, 1><<<gQKV, 256>>>(x, H_, nullptr, H_, nullptr, H_, H_,
                                     nullptr, nullptr, qa);

        dim3 gqk(N_ / GBN, N_ / GBM, B_ * NH_);       // (16, 16, 16)
        qk_tc<<<gqk, 256>>>(q, k, adjs, s);

        softmax_kernel<<<B_ * NH_ * N_, 256>>>(s);

        dim3 gav(DH_ / GBN, N_ / GBM, B_ * NH_);      // (1, 16, 16)
        gemm_tc<3, 2><<<gav, 256>>>(s, N_, v, H_, o, H_, N_, nullptr, nullptr);

        gemm_tc<0, 0><<<gHH, 256>>>(o, H_, Wo + wo, H_, y, H_, H_, bo + j * H_, nullptr);
        ln_kernel<<<B_ * N_, 256>>>(y, t, ln1g + j * H_, ln1b + j * H_);

        gemm_tc<1, 0><<<gFF, 256>>>(t, H_, W1 + w1o, FF_, h, FF_, H_,
                                    b1 + j * FF_, prelu + j * FF_);
        gemm_tc<2, 0><<<gHH, 256>>>(h, FF_, W2 + w2o, H_, y, H_, FF_,
                                    b2 + j * H_, t);
        ln_kernel<<<B_ * N_, 256>>>(y, x, ln2g + j * H_, ln2b + j * H_);
    }

    {
        size_t tot4 = (size_t)B_ * N_ * H_ / 4;
        copy_gents_kernel<<<(unsigned)((tot4 + 255) / 256), 256>>>(x, (float*)d_out);
        finalize_head_kernel<<<(B_ * N_ + 255) / 256, 256>>>(x, (float*)d_out);
    }
}